// round 13
// baseline (speedup 1.0000x reference)
#include <cuda_runtime.h>
#include <cuda_bf16.h>
#include <cstdint>

// BasisEncoder: out[b][q] = ((x[b] & 63) == q) ? 1.0f : 0.0f
// 256 MB pure store stream.
//
// R4-R12: STG.cs path alone -> 5.13 TB/s; TMA bulk path alone -> 5.29 TB/s;
// both leave DRAM at ~65% with nothing saturated -> hypothesis: each store
// path is limited by its own per-SM request queue (L1tex wavefronts vs TMA
// engine), not by a shared L2/DRAM wall. R13: drive BOTH paths concurrently.
// Each block owns 128 rows: rows [0,64) go through a 16 KB SMEM tile + one
// TMA bulk store; rows [64,128) go through v8 STG.cs while the TMA drains.

static __device__ __forceinline__ uint32_t smem_u32(const void* p) {
    uint32_t a;
    asm("{ .reg .u64 t; cvta.to.shared.u64 t, %1; cvt.u32.u64 %0, t; }"
        : "=r"(a) : "l"(p));
    return a;
}

__global__ void __launch_bounds__(256)
basis_encoder_kernel(const int* __restrict__ x,
                     float* __restrict__ out) {
    __shared__ __align__(128) float tile[64 * 64];     // 16 KB

    int t    = threadIdx.x;
    int row0 = blockIdx.x << 7;                        // 128 rows per block

    // ---- Phase A: fill SMEM tile for rows [row0, row0+64), commit TMA ----
    {
        float4* dst = reinterpret_cast<float4*>(tile);
        int qb = (t & 15) << 2;
#pragma unroll
        for (int k = 0; k < 4; k++) {
            int j   = t + k * 256;                     // float4 idx in tile
            int row = j >> 4;
            int idx = __ldg(&x[row0 + row]) & 63;      // (x%256)%64 == x&63
            float4 v;
            v.x = (idx == qb + 0) ? 1.0f : 0.0f;
            v.y = (idx == qb + 1) ? 1.0f : 0.0f;
            v.z = (idx == qb + 2) ? 1.0f : 0.0f;
            v.w = (idx == qb + 3) ? 1.0f : 0.0f;
            dst[j] = v;
        }
        asm volatile("fence.proxy.async.shared::cta;" ::: "memory");
        __syncthreads();
        if (t == 0) {
            uint32_t s = smem_u32(tile);
            const float* g = out + ((size_t)row0 << 6);
            asm volatile(
                "cp.async.bulk.global.shared::cta.bulk_group [%0], [%1], %2;"
                :: "l"(g), "r"(s), "n"(64 * 64 * 4)
                : "memory");
            asm volatile("cp.async.bulk.commit_group;" ::: "memory");
        }
    }

    // ---- Phase B: direct v8 STG.cs for rows [row0+64, row0+128) ----
    // 64 rows x 8 chunks(32B) = 512 chunks; 2 per thread. Overlaps TMA drain.
    {
        int srow0 = row0 + 64;
        int coff  = (t & 7) << 3;                      // col offset of chunk
#pragma unroll
        for (int k = 0; k < 2; k++) {
            int c   = t + k * 256;                     // chunk idx in half
            int row = c >> 3;
            int dlt = (__ldg(&x[srow0 + row]) & 63) - coff;
            float v0 = (dlt == 0) ? 1.0f : 0.0f;
            float v1 = (dlt == 1) ? 1.0f : 0.0f;
            float v2 = (dlt == 2) ? 1.0f : 0.0f;
            float v3 = (dlt == 3) ? 1.0f : 0.0f;
            float v4 = (dlt == 4) ? 1.0f : 0.0f;
            float v5 = (dlt == 5) ? 1.0f : 0.0f;
            float v6 = (dlt == 6) ? 1.0f : 0.0f;
            float v7 = (dlt == 7) ? 1.0f : 0.0f;
            float* p = out + (((size_t)srow0 << 6) + ((size_t)c << 3));
            asm volatile(
                "st.global.cs.v8.f32 [%0], {%1, %2, %3, %4, %5, %6, %7, %8};"
                :: "l"(p),
                   "f"(v0), "f"(v1), "f"(v2), "f"(v3),
                   "f"(v4), "f"(v5), "f"(v6), "f"(v7)
                : "memory");
        }
    }

    // SMEM must stay alive until the bulk read completes.
    if (t == 0)
        asm volatile("cp.async.bulk.wait_group.read 0;" ::: "memory");
}

extern "C" void kernel_launch(void* const* d_in, const int* in_sizes, int n_in,
                              void* d_out, int out_size) {
    const int* x   = (const int*)d_in[0];
    float*     out = (float*)d_out;

    int rows   = out_size >> 6;        // 1,048,576
    int blocks = rows >> 7;            // 8192 blocks of 128 rows

    basis_encoder_kernel<<<blocks, 256>>>(x, out);
}

// round 16
// speedup vs baseline: 1.1437x; 1.1437x over previous
#include <cuda_runtime.h>
#include <cuda_bf16.h>
#include <cstdint>

// BasisEncoder: out[b][q] = ((x[b] & 63) == q) ? 1.0f : 0.0f
// 256 MB pure store stream at the chip write-drain ceiling.
//
// Store-path matrix so far (ncu dur / DRAM-active):
//   STG.cs.v8        41.6us / 5.14 TB/s
//   STG default v8   56.9us / 3.72 TB/s   <- eviction policy worth 15us!
//   TMA default      40.2us / 5.29 TB/s
//   TMA+STG hybrid   41.3us / 5.14 TB/s   (paths do NOT add)
// Last untested cell: TMA with an explicit L2::evict_first cache hint
// (createpolicy + cp.async.bulk...L2::cache_hint), mirroring the .cs fix.
// Otherwise identical to the best kernel (R5: 32KB tile, one bulk store).

static __device__ __forceinline__ uint32_t smem_u32(const void* p) {
    uint32_t a;
    asm("{ .reg .u64 t; cvta.to.shared.u64 t, %1; cvt.u32.u64 %0, t; }"
        : "=r"(a) : "l"(p));
    return a;
}

__global__ void __launch_bounds__(256)
basis_encoder_kernel(const int* __restrict__ x,
                     float* __restrict__ out) {
    __shared__ __align__(128) float tile[128 * 64];    // 32 KB

    int t    = threadIdx.x;
    int row0 = blockIdx.x << 7;                        // 128 rows per block
    int qb   = (t & 15) << 2;                          // quad base col

    // Direct computed fill: 2048 float4 (128 rows x 16 quads), 8 per thread.
    float4* dst = reinterpret_cast<float4*>(tile);
#pragma unroll
    for (int k = 0; k < 8; k++) {
        int j   = t + k * 256;
        int row = j >> 4;
        int idx = __ldg(&x[row0 + row]) & 63;          // (x%256)%64 == x&63
        float4 v;
        v.x = (idx == qb + 0) ? 1.0f : 0.0f;
        v.y = (idx == qb + 1) ? 1.0f : 0.0f;
        v.z = (idx == qb + 2) ? 1.0f : 0.0f;
        v.w = (idx == qb + 3) ? 1.0f : 0.0f;
        dst[j] = v;
    }
    asm volatile("fence.proxy.async.shared::cta;" ::: "memory");
    __syncthreads();

    // One 32 KB bulk TMA store with an evict_first L2 policy.
    if (t == 0) {
        uint32_t s = smem_u32(tile);
        const float* g = out + ((size_t)row0 << 6);
        asm volatile(
            "{\n\t"
            ".reg .b64 pol;\n\t"
            "createpolicy.fractional.L2::evict_first.b64 pol, 1.0;\n\t"
            "cp.async.bulk.global.shared::cta.bulk_group.L2::cache_hint "
            "[%0], [%1], %2, pol;\n\t"
            "}"
            :: "l"(g), "r"(s), "n"(128 * 64 * 4)
            : "memory");
        asm volatile("cp.async.bulk.commit_group;" ::: "memory");
        asm volatile("cp.async.bulk.wait_group.read 0;" ::: "memory");
    }
}

extern "C" void kernel_launch(void* const* d_in, const int* in_sizes, int n_in,
                              void* d_out, int out_size) {
    const int* x   = (const int*)d_in[0];
    float*     out = (float*)d_out;

    int rows   = out_size >> 6;        // 1,048,576
    int blocks = rows >> 7;            // 8192 blocks of 128 rows

    basis_encoder_kernel<<<blocks, 256>>>(x, out);
}